// round 1
// baseline (speedup 1.0000x reference)
#include <cuda_runtime.h>

// Tile geometry: 192 threads, each owns one raw column for the vertical pass.
// Raw width RW=192 (incl. +-5 halo) -> TW=182 output columns, TH=16 output rows.
#define RW 192
#define TW 182
#define TH 16
#define RH 26          // TH + 10
#define VSTRIDE 197    // 192 padded; 197 % 32 == 5 -> conflict-free phase C
#define NTHREADS 192
#define IMG_W 512
#define IMG_H 512
#define PLANES 96      // 32 batch * 3 channels
#define NPIX 25165824.0f

// Gaussian(sigma=1.5, k=11) weights, normalized (matches float64 ref to ~1e-7)
__device__ __constant__ const float kDummy = 0.f; // (unused; keeps nvcc happy)

static constexpr float W0 = 0.00102838f;
static constexpr float W1 = 0.00759876f;
static constexpr float W2 = 0.03600077f;
static constexpr float W3 = 0.10936069f;
static constexpr float W4 = 0.21300553f;
static constexpr float W5 = 0.26601172f;

static constexpr float C1V = 0.0001f;   // 0.01^2
static constexpr float C2V = 0.0009f;   // 0.03^2

__device__ float g_accum;

__device__ __forceinline__ float wgt(int k) {
    // k in [0,10], symmetric
    switch (k) {
        case 0: case 10: return W0;
        case 1: case 9:  return W1;
        case 2: case 8:  return W2;
        case 3: case 7:  return W3;
        case 4: case 6:  return W4;
        default:         return W5;
    }
}

__global__ void __launch_bounds__(NTHREADS)
ssim_main(const float* __restrict__ img1, const float* __restrict__ img2) {
    extern __shared__ float v[];   // [5][TH][VSTRIDE]

    const int tx = threadIdx.x;
    const int plane = blockIdx.z;
    const int x0 = blockIdx.x * TW;
    const int y0 = blockIdx.y * TH;

    const float* __restrict__ p1 = img1 + (size_t)plane * (IMG_W * IMG_H);
    const float* __restrict__ p2 = img2 + (size_t)plane * (IMG_W * IMG_H);

    const int gx = x0 - 5 + tx;
    const bool xok = (gx >= 0) && (gx < IMG_W);

    float acc[5][11];
#pragma unroll
    for (int q = 0; q < 5; q++)
#pragma unroll
        for (int j = 0; j < 11; j++) acc[q][j] = 0.f;

    // ---------- Phase B: vertical blur, global -> smem, transposed accumulation ----------
#pragma unroll
    for (int r = 0; r < RH; r++) {
        const int gy = y0 - 5 + r;
        const bool ok = xok && (gy >= 0) && (gy < IMG_H);
        float a = 0.f, b = 0.f;
        if (ok) {
            const int idx = gy * IMG_W + gx;
            a = __ldg(p1 + idx);
            b = __ldg(p2 + idx);
        }
        float pq[5];
        pq[0] = a; pq[1] = b; pq[2] = a * a; pq[3] = b * b; pq[4] = a * b;
#pragma unroll
        for (int k = 0; k < 11; k++) {
            const int o = r - k;            // output row this tap feeds
            if (o >= 0 && o < TH) {
                const int j = o % 11;       // compile-time after unroll
#pragma unroll
                for (int q = 0; q < 5; q++)
                    acc[q][j] = fmaf(pq[q], wgt(k), acc[q][j]);
            }
        }
        if (r >= 10) {
            const int o = r - 10;
            const int j = o % 11;
#pragma unroll
            for (int q = 0; q < 5; q++) {
                v[(q * TH + o) * VSTRIDE + tx] = acc[q][j];
                acc[q][j] = 0.f;
            }
        }
    }
    __syncthreads();

    // ---------- Phase C: horizontal blur + SSIM epilogue + local sum ----------
    const int row = tx & 15;     // 0..15
    const int seg = tx >> 4;     // 0..11, each covers 16 consecutive x outputs
    const int xbase = seg * 16;

#pragma unroll
    for (int q = 0; q < 5; q++)
#pragma unroll
        for (int j = 0; j < 11; j++) acc[q][j] = 0.f;

    float lsum = 0.f;
#pragma unroll
    for (int i = 0; i < 26; i++) {
        const int c = xbase + i;
        const bool cok = (c < RW);
        float pq[5];
#pragma unroll
        for (int q = 0; q < 5; q++)
            pq[q] = cok ? v[(q * TH + row) * VSTRIDE + c] : 0.f;
#pragma unroll
        for (int k = 0; k < 11; k++) {
            const int xo = i - k;           // local output index in [0,16)
            if (xo >= 0 && xo < 16) {
                const int j = xo % 11;
#pragma unroll
                for (int q = 0; q < 5; q++)
                    acc[q][j] = fmaf(pq[q], wgt(k), acc[q][j]);
            }
        }
        if (i >= 10) {
            const int xo = i - 10;
            const int j = xo % 11;
            const float mu1 = acc[0][j], mu2 = acc[1][j];
            const float e11 = acc[2][j], e22 = acc[3][j], e12 = acc[4][j];
#pragma unroll
            for (int q = 0; q < 5; q++) acc[q][j] = 0.f;

            const int xout = xbase + xo;
            if (xout < TW && (x0 + xout) < IMG_W) {
                const float m11 = mu1 * mu1;
                const float m22 = mu2 * mu2;
                const float m12 = mu1 * mu2;
                const float s1  = e11 - m11;
                const float s2  = e22 - m22;
                const float s12 = e12 - m12;
                const float num = (2.f * m12 + C1V) * (2.f * s12 + C2V);
                const float den = (m11 + m22 + C1V) * (s1 + s2 + C2V);
                lsum += __fdividef(num, den);
            }
        }
    }

    // ---------- reduction ----------
#pragma unroll
    for (int off = 16; off > 0; off >>= 1)
        lsum += __shfl_xor_sync(0xffffffffu, lsum, off);
    if ((tx & 31) == 0)
        atomicAdd(&g_accum, lsum);
}

__global__ void ssim_init() { g_accum = 0.f; }

__global__ void ssim_final(float* out) {
    out[0] = 1.0f - g_accum * (1.0f / NPIX);
}

extern "C" void kernel_launch(void* const* d_in, const int* in_sizes, int n_in,
                              void* d_out, int out_size) {
    const float* img1 = (const float*)d_in[0];
    const float* img2 = (const float*)d_in[1];

    const int smem = 5 * TH * VSTRIDE * (int)sizeof(float);  // 63,040 B
    cudaFuncSetAttribute(ssim_main, cudaFuncAttributeMaxDynamicSharedMemorySize, smem);

    ssim_init<<<1, 1>>>();
    dim3 grid((IMG_W + TW - 1) / TW, IMG_H / TH, PLANES);    // (3, 32, 96)
    ssim_main<<<grid, NTHREADS, smem>>>(img1, img2);
    ssim_final<<<1, 1>>>((float*)d_out);
}